// round 14
// baseline (speedup 1.0000x reference)
#include <cuda_runtime.h>

// GRU4Rec user module: ragged GRU(128) -> dense(128) -> L2 normalize.
// Inputs: x f32[T,128], offset i32[B] (i64 auto-detect), W_ih f32[384,128],
//         W_hh f32[384,128], W_dense f32[128,128], b_dense f32[128]
// Output: f32[B,128]
//
// R14: NSEQ=3 (register-safe: ~160 live regs), single-pass gates/dense
// (384 = 3*128), j-loop unroll capped at 8 (compile-light; R10-proven).
// k_xproj = proven R7 4-token version. Counting-sort length grouping.

#define DIMD 128
#define DIMH 128
#define G3   384
#define MAXB 4096
#define MAXLEN 200
#define NSEQ 3

__device__ float g_xproj[(size_t)2048 * MAXLEN * G3];
__device__ int g_off[MAXB];
__device__ int g_len[MAXB];
__device__ int g_order[MAXB];

__device__ __forceinline__ void ffma2(unsigned long long &acc,
                                      unsigned long long a,
                                      unsigned long long b) {
    asm("fma.rn.f32x2 %0, %1, %2, %0;" : "+l"(acc) : "l"(a), "l"(b));
}
__device__ __forceinline__ float f2lo(unsigned long long v) {
    return __uint_as_float((unsigned int)v);
}
__device__ __forceinline__ float f2hi(unsigned long long v) {
    return __uint_as_float((unsigned int)(v >> 32));
}
__device__ __forceinline__ float rcp_approx(float x) {
    float r;
    asm("rcp.approx.f32 %0, %1;" : "=f"(r) : "f"(x));
    return r;
}
__device__ __forceinline__ float fast_sigmoid(float v) {
    return rcp_approx(1.0f + __expf(-v));
}
__device__ __forceinline__ float fast_tanh(float v) {
    float av = fabsf(v);
    float e = __expf(-2.0f * av);
    float m = (1.0f - e) * rcp_approx(1.0f + e);
    return copysignf(m, v);
}
__device__ __forceinline__ int load_off(const void* p, int i, bool is64) {
    return is64 ? (int)((const long long*)p)[i] : ((const int*)p)[i];
}
__device__ __forceinline__ int sel3(int s, int a, int b, int c) {
    return (s == 0) ? a : (s == 1) ? b : c;
}

// ---------------------------------------------------------------------------
// K0: offsets/lengths + counting sort of sequence indices by length.
// ---------------------------------------------------------------------------
__global__ void k_sort(const void* __restrict__ off_raw, int T, int B) {
    __shared__ int s_cnt[MAXLEN + 1];
    const int tid = threadIdx.x;
    const bool is64 = (B > 1) && (((const int*)off_raw)[1] == 0);

    for (int i = tid; i <= MAXLEN; i += blockDim.x) s_cnt[i] = 0;
    __syncthreads();

    for (int i = tid; i < B; i += blockDim.x) {
        int o  = load_off(off_raw, i, is64);
        int oe = (i + 1 < B) ? load_off(off_raw, i + 1, is64) : T;
        int l = oe - o;
        if (o < 0) o = 0;
        if (l < 0) l = 0;
        if (l > MAXLEN) l = MAXLEN;
        g_off[i] = o;
        g_len[i] = l;
        atomicAdd(&s_cnt[l], 1);
    }
    __syncthreads();

    if (tid == 0) {
        int run = 0;
        for (int j = 0; j <= MAXLEN; j++) { int c = s_cnt[j]; s_cnt[j] = run; run += c; }
    }
    __syncthreads();

    for (int i = tid; i < B; i += blockDim.x) {
        int pos = atomicAdd(&s_cnt[g_len[i]], 1);
        g_order[pos] = i;
    }
}

// ---------------------------------------------------------------------------
// K1: x_proj = x @ W_ih^T. 4-token tiles (exact R7 version, proven).
// ---------------------------------------------------------------------------
__global__ __launch_bounds__(384, 1)
void k_xproj(const float* __restrict__ x,
             const float* __restrict__ W_ih,
             int T, int chunk) {
    const int g = threadIdx.x;

    int t0 = blockIdx.x * chunk;
    int t1 = min(T, t0 + chunk);
    if (t0 >= t1) return;  // uniform across block

    unsigned long long Wr[64];
    {
        const unsigned long long* Wp =
            (const unsigned long long*)(W_ih + (size_t)g * DIMD);
        #pragma unroll
        for (int j = 0; j < 64; j++) Wr[j] = Wp[j];
    }

    __shared__ __align__(16) float sx[2][4][DIMD];

    if (g < 128) {
        int tk = t0 + (g >> 5);
        if (tk < t1)
            ((float4*)sx[0][g >> 5])[g & 31] =
                ((const float4*)x)[(size_t)tk * 32 + (g & 31)];
    }
    __syncthreads();

    int buf = 0;
    for (int ts = t0; ts < t1; ts += 4) {
        if (g < 128) {
            int tk = ts + 4 + (g >> 5);
            if (tk < t1)
                ((float4*)sx[buf ^ 1][g >> 5])[g & 31] =
                    ((const float4*)x)[(size_t)tk * 32 + (g & 31)];
        }

        unsigned long long a0[4], a1[4];
        #pragma unroll
        for (int k = 0; k < 4; k++) { a0[k] = 0ull; a1[k] = 0ull; }

        const ulonglong2* hp0 = (const ulonglong2*)sx[buf][0];
        const ulonglong2* hp1 = (const ulonglong2*)sx[buf][1];
        const ulonglong2* hp2 = (const ulonglong2*)sx[buf][2];
        const ulonglong2* hp3 = (const ulonglong2*)sx[buf][3];
        #pragma unroll
        for (int j = 0; j < 32; j++) {
            ulonglong2 v0 = hp0[j], v1 = hp1[j], v2 = hp2[j], v3 = hp3[j];
            ffma2(a0[0], Wr[2 * j], v0.x);  ffma2(a1[0], Wr[2 * j + 1], v0.y);
            ffma2(a0[1], Wr[2 * j], v1.x);  ffma2(a1[1], Wr[2 * j + 1], v1.y);
            ffma2(a0[2], Wr[2 * j], v2.x);  ffma2(a1[2], Wr[2 * j + 1], v2.y);
            ffma2(a0[3], Wr[2 * j], v3.x);  ffma2(a1[3], Wr[2 * j + 1], v3.y);
        }
        #pragma unroll
        for (int k = 0; k < 4; k++) {
            int tk = ts + k;
            if (tk < t1) {
                float s = (f2lo(a0[k]) + f2hi(a0[k])) + (f2lo(a1[k]) + f2hi(a1[k]));
                g_xproj[(size_t)tk * G3 + g] = s;
            }
        }

        __syncthreads();
        buf ^= 1;
    }
}

// ---------------------------------------------------------------------------
// K2 v5: GRU recurrence, 3 length-sorted sequences per block (384 threads).
// Thread i owns W_hh row i (64 ull) reused across the 3 sequences.
// Single-pass gates (384 = 3 x 128) and single-pass dense.
// j-loop unroll capped at 8 (compile-light).
// ---------------------------------------------------------------------------
__global__ __launch_bounds__(384, 1)
void k_rec(const float* __restrict__ W_hh,
           const float* __restrict__ W_dense,
           const float* __restrict__ b_dense,
           float* __restrict__ out,
           int B) {
    const int i = threadIdx.x;
    const int base = NSEQ * blockIdx.x;

    const int seq0 = g_order[base];
    const int seq1 = (base + 1 < B) ? g_order[base + 1] : -1;
    const int seq2 = (base + 2 < B) ? g_order[base + 2] : -1;

    const int len0 = g_len[seq0];
    const int len1 = (seq1 >= 0) ? g_len[seq1] : 0;
    const int len2 = (seq2 >= 0) ? g_len[seq2] : 0;
    const int off0 = g_off[seq0];
    const int off1 = (seq1 >= 0) ? g_off[seq1] : 0;
    const int off2 = (seq2 >= 0) ? g_off[seq2] : 0;
    const int lmax = max(max(len0, len1), len2);

    unsigned long long Wr[64];
    {
        const unsigned long long* Wp =
            (const unsigned long long*)(W_hh + (size_t)i * DIMH);
        #pragma unroll
        for (int j = 0; j < 64; j++) Wr[j] = Wp[j];
    }

    __shared__ __align__(16) float sh_h[NSEQ][DIMH];
    __shared__ float sh_pre[NSEQ][G3];
    __shared__ float sh_xgn[NSEQ][DIMH];
    __shared__ float sred[12];

    if (i < DIMH) {
        sh_h[0][i] = 0.0f; sh_h[1][i] = 0.0f; sh_h[2][i] = 0.0f;
    }
    __syncthreads();

    const float* xp0 = g_xproj + (size_t)off0 * G3 + i;
    const float* xp1 = g_xproj + (size_t)off1 * G3 + i;
    const float* xp2 = g_xproj + (size_t)off2 * G3 + i;

    float xv0 = (0 < len0) ? xp0[0] : 0.0f;
    float xv1 = (0 < len1) ? xp1[0] : 0.0f;
    float xv2 = (0 < len2) ? xp2[0] : 0.0f;

    for (int t = 0; t < lmax; t++) {
        float xn0 = (t + 1 < len0) ? xp0[(size_t)(t + 1) * G3] : 0.0f;
        float xn1 = (t + 1 < len1) ? xp1[(size_t)(t + 1) * G3] : 0.0f;
        float xn2 = (t + 1 < len2) ? xp2[(size_t)(t + 1) * G3] : 0.0f;

        unsigned long long a00 = 0ull, a01 = 0ull;
        unsigned long long a10 = 0ull, a11 = 0ull;
        unsigned long long a20 = 0ull, a21 = 0ull;
        const ulonglong2* hp0 = (const ulonglong2*)sh_h[0];
        const ulonglong2* hp1 = (const ulonglong2*)sh_h[1];
        const ulonglong2* hp2 = (const ulonglong2*)sh_h[2];
        #pragma unroll 8
        for (int j = 0; j < 32; j++) {
            unsigned long long w0 = Wr[2 * j], w1 = Wr[2 * j + 1];
            ulonglong2 v0 = hp0[j];              // broadcast LDS.128
            ulonglong2 v1 = hp1[j];
            ulonglong2 v2 = hp2[j];
            ffma2(a00, w0, v0.x);  ffma2(a01, w1, v0.y);
            ffma2(a10, w0, v1.x);  ffma2(a11, w1, v1.y);
            ffma2(a20, w0, v2.x);  ffma2(a21, w1, v2.y);
        }
        float hg0 = (f2lo(a00) + f2hi(a00)) + (f2lo(a01) + f2hi(a01));
        float hg1 = (f2lo(a10) + f2hi(a10)) + (f2lo(a11) + f2hi(a11));
        float hg2 = (f2lo(a20) + f2hi(a20)) + (f2lo(a21) + f2hi(a21));

        if (i < 2 * DIMH) {
            sh_pre[0][i] = hg0 + xv0;            // r,z pre-activations
            sh_pre[1][i] = hg1 + xv1;
            sh_pre[2][i] = hg2 + xv2;
        } else {
            sh_pre[0][i] = hg0;                  // n: hg separate (r scales hg)
            sh_pre[1][i] = hg1;
            sh_pre[2][i] = hg2;
            sh_xgn[0][i - 2 * DIMH] = xv0;
            sh_xgn[1][i - 2 * DIMH] = xv1;
            sh_xgn[2][i - 2 * DIMH] = xv2;
        }
        __syncthreads();

        // gates: 384 units (3 seqs x 128), single pass
        {
            int s = i >> 7;                      // 0..2, uniform per warp
            int j = i & (DIMH - 1);
            int ls = sel3(s, len0, len1, len2);
            if (t < ls) {
                float rg = fast_sigmoid(sh_pre[s][j]);
                float zg = fast_sigmoid(sh_pre[s][DIMH + j]);
                float n  = fast_tanh(fmaf(rg, sh_pre[s][2 * DIMH + j], sh_xgn[s][j]));
                float ho = sh_h[s][j];
                sh_h[s][j] = fmaf(zg, ho - n, n);
            }
        }
        __syncthreads();

        xv0 = xn0; xv1 = xn1; xv2 = xn2;
    }

    // dense + L2 normalize: 384 outputs (3 seqs x 128), single pass.
    const int s1 = i >> 7;
    const int d1 = i & (DIMH - 1);
    float val;
    {
        unsigned long long a0 = 0ull, a1 = 0ull;
        const unsigned long long* Wd =
            (const unsigned long long*)(W_dense + (size_t)d1 * DIMH);
        const ulonglong2* hp = (const ulonglong2*)sh_h[s1];
        #pragma unroll 8
        for (int j = 0; j < 32; j++) {
            ulonglong2 hv = hp[j];
            ffma2(a0, Wd[2 * j],     hv.x);
            ffma2(a1, Wd[2 * j + 1], hv.y);
        }
        val = (f2lo(a0) + f2hi(a0)) + (f2lo(a1) + f2hi(a1)) + b_dense[d1];

        float ss = val * val;
        #pragma unroll
        for (int sh = 16; sh > 0; sh >>= 1)
            ss += __shfl_xor_sync(0xffffffffu, ss, sh);
        if ((i & 31) == 0) sred[i >> 5] = ss;
    }
    __syncthreads();

    {
        int b4 = s1 * 4;
        float ss = sred[b4] + sred[b4 + 1] + sred[b4 + 2] + sred[b4 + 3];
        float nrm = fmaxf(sqrtf(ss), 1e-12f);
        int sq = sel3(s1, seq0, seq1, seq2);
        if (sq >= 0)
            out[(size_t)sq * DIMD + d1] = val / nrm;
    }
}

// ---------------------------------------------------------------------------
extern "C" void kernel_launch(void* const* d_in, const int* in_sizes, int n_in,
                              void* d_out, int out_size) {
    const float* x       = (const float*)d_in[0];
    const void*  off     = d_in[1];                   // int32 or int64
    const float* W_ih    = (const float*)d_in[2];
    const float* W_hh    = (const float*)d_in[3];
    const float* W_dense = (const float*)d_in[4];
    const float* b_dense = (const float*)d_in[5];
    float*       out     = (float*)d_out;

    const int T = in_sizes[0] / DIMD;   // total tokens
    const int B = out_size / DIMD;      // number of sequences

    const int G1 = 1184;                // 8 waves at 1 block/SM on 148 SMs
    const int chunk = (T + G1 - 1) / G1;
    k_xproj<<<G1, 384>>>(x, W_ih, T, chunk);

    k_sort<<<1, 256>>>(off, T, B);

    const int G2 = (B + NSEQ - 1) / NSEQ;
    k_rec<<<G2, 384>>>(W_hh, W_dense, b_dense, out, B);
}

// round 15
// speedup vs baseline: 1.2922x; 1.2922x over previous
#include <cuda_runtime.h>

// GRU4Rec user module: ragged GRU(128) -> dense(128) -> L2 normalize.
// Inputs: x f32[T,128], offset i32[B] (i64 auto-detect), W_ih f32[384,128],
//         W_hh f32[384,128], W_dense f32[128,128], b_dense f32[128]
// Output: f32[B,128]
//
// R15 = R14 with the local-memory bug fixed: k_rec j-loop FULLY unrolled so
// Wr[] stays register-resident (unroll-8 made Wr[2*j] dynamically indexed ->
// ptxas demoted weights to local memory -> LDL every step; R10+R14 evidence).
// NSEQ=3, single-pass gates/dense (384 = 3*128). k_xproj = proven R7.

#define DIMD 128
#define DIMH 128
#define G3   384
#define MAXB 4096
#define MAXLEN 200
#define NSEQ 3

__device__ float g_xproj[(size_t)2048 * MAXLEN * G3];
__device__ int g_off[MAXB];
__device__ int g_len[MAXB];
__device__ int g_order[MAXB];

__device__ __forceinline__ void ffma2(unsigned long long &acc,
                                      unsigned long long a,
                                      unsigned long long b) {
    asm("fma.rn.f32x2 %0, %1, %2, %0;" : "+l"(acc) : "l"(a), "l"(b));
}
__device__ __forceinline__ float f2lo(unsigned long long v) {
    return __uint_as_float((unsigned int)v);
}
__device__ __forceinline__ float f2hi(unsigned long long v) {
    return __uint_as_float((unsigned int)(v >> 32));
}
__device__ __forceinline__ float rcp_approx(float x) {
    float r;
    asm("rcp.approx.f32 %0, %1;" : "=f"(r) : "f"(x));
    return r;
}
__device__ __forceinline__ float fast_sigmoid(float v) {
    return rcp_approx(1.0f + __expf(-v));
}
__device__ __forceinline__ float fast_tanh(float v) {
    float av = fabsf(v);
    float e = __expf(-2.0f * av);
    float m = (1.0f - e) * rcp_approx(1.0f + e);
    return copysignf(m, v);
}
__device__ __forceinline__ int load_off(const void* p, int i, bool is64) {
    return is64 ? (int)((const long long*)p)[i] : ((const int*)p)[i];
}
__device__ __forceinline__ int sel3(int s, int a, int b, int c) {
    return (s == 0) ? a : (s == 1) ? b : c;
}

// ---------------------------------------------------------------------------
// K0: offsets/lengths + counting sort of sequence indices by length.
// ---------------------------------------------------------------------------
__global__ void k_sort(const void* __restrict__ off_raw, int T, int B) {
    __shared__ int s_cnt[MAXLEN + 1];
    const int tid = threadIdx.x;
    const bool is64 = (B > 1) && (((const int*)off_raw)[1] == 0);

    for (int i = tid; i <= MAXLEN; i += blockDim.x) s_cnt[i] = 0;
    __syncthreads();

    for (int i = tid; i < B; i += blockDim.x) {
        int o  = load_off(off_raw, i, is64);
        int oe = (i + 1 < B) ? load_off(off_raw, i + 1, is64) : T;
        int l = oe - o;
        if (o < 0) o = 0;
        if (l < 0) l = 0;
        if (l > MAXLEN) l = MAXLEN;
        g_off[i] = o;
        g_len[i] = l;
        atomicAdd(&s_cnt[l], 1);
    }
    __syncthreads();

    if (tid == 0) {
        int run = 0;
        for (int j = 0; j <= MAXLEN; j++) { int c = s_cnt[j]; s_cnt[j] = run; run += c; }
    }
    __syncthreads();

    for (int i = tid; i < B; i += blockDim.x) {
        int pos = atomicAdd(&s_cnt[g_len[i]], 1);
        g_order[pos] = i;
    }
}

// ---------------------------------------------------------------------------
// K1: x_proj = x @ W_ih^T. 4-token tiles (exact R7 version, proven 809us).
// ---------------------------------------------------------------------------
__global__ __launch_bounds__(384, 1)
void k_xproj(const float* __restrict__ x,
             const float* __restrict__ W_ih,
             int T, int chunk) {
    const int g = threadIdx.x;

    int t0 = blockIdx.x * chunk;
    int t1 = min(T, t0 + chunk);
    if (t0 >= t1) return;  // uniform across block

    unsigned long long Wr[64];
    {
        const unsigned long long* Wp =
            (const unsigned long long*)(W_ih + (size_t)g * DIMD);
        #pragma unroll
        for (int j = 0; j < 64; j++) Wr[j] = Wp[j];
    }

    __shared__ __align__(16) float sx[2][4][DIMD];

    if (g < 128) {
        int tk = t0 + (g >> 5);
        if (tk < t1)
            ((float4*)sx[0][g >> 5])[g & 31] =
                ((const float4*)x)[(size_t)tk * 32 + (g & 31)];
    }
    __syncthreads();

    int buf = 0;
    for (int ts = t0; ts < t1; ts += 4) {
        if (g < 128) {
            int tk = ts + 4 + (g >> 5);
            if (tk < t1)
                ((float4*)sx[buf ^ 1][g >> 5])[g & 31] =
                    ((const float4*)x)[(size_t)tk * 32 + (g & 31)];
        }

        unsigned long long a0[4], a1[4];
        #pragma unroll
        for (int k = 0; k < 4; k++) { a0[k] = 0ull; a1[k] = 0ull; }

        const ulonglong2* hp0 = (const ulonglong2*)sx[buf][0];
        const ulonglong2* hp1 = (const ulonglong2*)sx[buf][1];
        const ulonglong2* hp2 = (const ulonglong2*)sx[buf][2];
        const ulonglong2* hp3 = (const ulonglong2*)sx[buf][3];
        #pragma unroll
        for (int j = 0; j < 32; j++) {
            ulonglong2 v0 = hp0[j], v1 = hp1[j], v2 = hp2[j], v3 = hp3[j];
            ffma2(a0[0], Wr[2 * j], v0.x);  ffma2(a1[0], Wr[2 * j + 1], v0.y);
            ffma2(a0[1], Wr[2 * j], v1.x);  ffma2(a1[1], Wr[2 * j + 1], v1.y);
            ffma2(a0[2], Wr[2 * j], v2.x);  ffma2(a1[2], Wr[2 * j + 1], v2.y);
            ffma2(a0[3], Wr[2 * j], v3.x);  ffma2(a1[3], Wr[2 * j + 1], v3.y);
        }
        #pragma unroll
        for (int k = 0; k < 4; k++) {
            int tk = ts + k;
            if (tk < t1) {
                float s = (f2lo(a0[k]) + f2hi(a0[k])) + (f2lo(a1[k]) + f2hi(a1[k]));
                g_xproj[(size_t)tk * G3 + g] = s;
            }
        }

        __syncthreads();
        buf ^= 1;
    }
}

// ---------------------------------------------------------------------------
// K2 v5b: GRU recurrence, 3 length-sorted sequences per block (384 threads).
// Thread i owns W_hh row i (64 ull, register-resident: j-loop FULLY unrolled)
// and reuses it across the 3 sequences. Single-pass gates and dense.
// ---------------------------------------------------------------------------
__global__ __launch_bounds__(384, 1)
void k_rec(const float* __restrict__ W_hh,
           const float* __restrict__ W_dense,
           const float* __restrict__ b_dense,
           float* __restrict__ out,
           int B) {
    const int i = threadIdx.x;
    const int base = NSEQ * blockIdx.x;

    const int seq0 = g_order[base];
    const int seq1 = (base + 1 < B) ? g_order[base + 1] : -1;
    const int seq2 = (base + 2 < B) ? g_order[base + 2] : -1;

    const int len0 = g_len[seq0];
    const int len1 = (seq1 >= 0) ? g_len[seq1] : 0;
    const int len2 = (seq2 >= 0) ? g_len[seq2] : 0;
    const int off0 = g_off[seq0];
    const int off1 = (seq1 >= 0) ? g_off[seq1] : 0;
    const int off2 = (seq2 >= 0) ? g_off[seq2] : 0;
    const int lmax = max(max(len0, len1), len2);

    unsigned long long Wr[64];
    {
        const unsigned long long* Wp =
            (const unsigned long long*)(W_hh + (size_t)i * DIMH);
        #pragma unroll
        for (int j = 0; j < 64; j++) Wr[j] = Wp[j];
    }

    __shared__ __align__(16) float sh_h[NSEQ][DIMH];
    __shared__ float sh_pre[NSEQ][G3];
    __shared__ float sh_xgn[NSEQ][DIMH];
    __shared__ float sred[12];

    if (i < DIMH) {
        sh_h[0][i] = 0.0f; sh_h[1][i] = 0.0f; sh_h[2][i] = 0.0f;
    }
    __syncthreads();

    const float* xp0 = g_xproj + (size_t)off0 * G3 + i;
    const float* xp1 = g_xproj + (size_t)off1 * G3 + i;
    const float* xp2 = g_xproj + (size_t)off2 * G3 + i;

    float xv0 = (0 < len0) ? xp0[0] : 0.0f;
    float xv1 = (0 < len1) ? xp1[0] : 0.0f;
    float xv2 = (0 < len2) ? xp2[0] : 0.0f;

    for (int t = 0; t < lmax; t++) {
        float xn0 = (t + 1 < len0) ? xp0[(size_t)(t + 1) * G3] : 0.0f;
        float xn1 = (t + 1 < len1) ? xp1[(size_t)(t + 1) * G3] : 0.0f;
        float xn2 = (t + 1 < len2) ? xp2[(size_t)(t + 1) * G3] : 0.0f;

        unsigned long long a00 = 0ull, a01 = 0ull;
        unsigned long long a10 = 0ull, a11 = 0ull;
        unsigned long long a20 = 0ull, a21 = 0ull;
        const ulonglong2* hp0 = (const ulonglong2*)sh_h[0];
        const ulonglong2* hp1 = (const ulonglong2*)sh_h[1];
        const ulonglong2* hp2 = (const ulonglong2*)sh_h[2];
        #pragma unroll
        for (int j = 0; j < 32; j++) {
            unsigned long long w0 = Wr[2 * j], w1 = Wr[2 * j + 1];
            ulonglong2 v0 = hp0[j];              // broadcast LDS.128
            ulonglong2 v1 = hp1[j];
            ulonglong2 v2 = hp2[j];
            ffma2(a00, w0, v0.x);  ffma2(a01, w1, v0.y);
            ffma2(a10, w0, v1.x);  ffma2(a11, w1, v1.y);
            ffma2(a20, w0, v2.x);  ffma2(a21, w1, v2.y);
        }
        float hg0 = (f2lo(a00) + f2hi(a00)) + (f2lo(a01) + f2hi(a01));
        float hg1 = (f2lo(a10) + f2hi(a10)) + (f2lo(a11) + f2hi(a11));
        float hg2 = (f2lo(a20) + f2hi(a20)) + (f2lo(a21) + f2hi(a21));

        if (i < 2 * DIMH) {
            sh_pre[0][i] = hg0 + xv0;            // r,z pre-activations
            sh_pre[1][i] = hg1 + xv1;
            sh_pre[2][i] = hg2 + xv2;
        } else {
            sh_pre[0][i] = hg0;                  // n: hg separate (r scales hg)
            sh_pre[1][i] = hg1;
            sh_pre[2][i] = hg2;
            sh_xgn[0][i - 2 * DIMH] = xv0;
            sh_xgn[1][i - 2 * DIMH] = xv1;
            sh_xgn[2][i - 2 * DIMH] = xv2;
        }
        __syncthreads();

        // gates: 384 units (3 seqs x 128), single pass
        {
            int s = i >> 7;                      // 0..2, uniform per warp
            int j = i & (DIMH - 1);
            int ls = sel3(s, len0, len1, len2);
            if (t < ls) {
                float rg = fast_sigmoid(sh_pre[s][j]);
                float zg = fast_sigmoid(sh_pre[s][DIMH + j]);
                float n  = fast_tanh(fmaf(rg, sh_pre[s][2 * DIMH + j], sh_xgn[s][j]));
                float ho = sh_h[s][j];
                sh_h[s][j] = fmaf(zg, ho - n, n);
            }
        }
        __syncthreads();

        xv0 = xn0; xv1 = xn1; xv2 = xn2;
    }

    // dense + L2 normalize: 384 outputs (3 seqs x 128), single pass.
    const int s1 = i >> 7;
    const int d1 = i & (DIMH - 1);
    float val;
    {
        unsigned long long a0 = 0ull, a1 = 0ull;
        const unsigned long long* Wd =
            (const unsigned long long*)(W_dense + (size_t)d1 * DIMH);
        const ulonglong2* hp = (const ulonglong2*)sh_h[s1];
        #pragma unroll
        for (int j = 0; j < 32; j++) {
            ulonglong2 hv = hp[j];
            ffma2(a0, Wd[2 * j],     hv.x);
            ffma2(a1, Wd[2 * j + 1], hv.y);
        }
        val = (f2lo(a0) + f2hi(a0)) + (f2lo(a1) + f2hi(a1)) + b_dense[d1];

        float ss = val * val;
        #pragma unroll
        for (int sh = 16; sh > 0; sh >>= 1)
            ss += __shfl_xor_sync(0xffffffffu, ss, sh);
        if ((i & 31) == 0) sred[i >> 5] = ss;
    }
    __syncthreads();

    {
        int b4 = s1 * 4;
        float ss = sred[b4] + sred[b4 + 1] + sred[b4 + 2] + sred[b4 + 3];
        float nrm = fmaxf(sqrtf(ss), 1e-12f);
        int sq = sel3(s1, seq0, seq1, seq2);
        if (sq >= 0)
            out[(size_t)sq * DIMD + d1] = val / nrm;
    }
}

// ---------------------------------------------------------------------------
extern "C" void kernel_launch(void* const* d_in, const int* in_sizes, int n_in,
                              void* d_out, int out_size) {
    const float* x       = (const float*)d_in[0];
    const void*  off     = d_in[1];                   // int32 or int64
    const float* W_ih    = (const float*)d_in[2];
    const float* W_hh    = (const float*)d_in[3];
    const float* W_dense = (const float*)d_in[4];
    const float* b_dense = (const float*)d_in[5];
    float*       out     = (float*)d_out;

    const int T = in_sizes[0] / DIMD;   // total tokens
    const int B = out_size / DIMD;      // number of sequences

    const int G1 = 1184;                // 8 waves at 1 block/SM on 148 SMs
    const int chunk = (T + G1 - 1) / G1;
    k_xproj<<<G1, 384>>>(x, W_ih, T, chunk);

    k_sort<<<1, 256>>>(off, T, B);

    const int G2 = (B + NSEQ - 1) / NSEQ;
    k_rec<<<G2, 384>>>(W_hh, W_dense, b_dense, out, B);
}